// round 1
// baseline (speedup 1.0000x reference)
#include <cuda_runtime.h>
#include <cuda_bf16.h>
#include <cstdint>

// ---------------------------------------------------------------------------
// GCN: h1 = relu((ÂX)W1 + b1); h2 = relu((Âh1)W2 + b2); pooled mean; MLP head.
// Â = D^-1/2 (A+I) D^-1/2. Aggregate-before-transform halves layer-1 scatter.
// ---------------------------------------------------------------------------

#define MAX_NODES 100000
#define HID 256
#define NGRAPH 2048

__device__ float g_bufA[(size_t)MAX_NODES * HID];   // agg_x (128 cols) / agg_h (256 cols)
__device__ float g_bufB[(size_t)MAX_NODES * HID];   // h1 / h2
__device__ float g_dinv[MAX_NODES];                 // deg -> dinv
__device__ float g_pool[NGRAPH * HID];
__device__ float g_cnt[NGRAPH];

// ---------------- degree / normalization ----------------
__global__ void k_deg_init(float* deg, int n) {
    int i = blockIdx.x * blockDim.x + threadIdx.x;
    if (i < n) deg[i] = 1.0f;   // self-loop
}

__global__ void k_deg_edges(const int* __restrict__ dst, float* __restrict__ deg, int nE) {
    int i = blockIdx.x * blockDim.x + threadIdx.x;
    if (i < nE) atomicAdd(&deg[dst[i]], 1.0f);
}

__global__ void k_make_dinv(float* deg, int n) {
    int i = blockIdx.x * blockDim.x + threadIdx.x;
    if (i < n) deg[i] = rsqrtf(deg[i]);   // deg >= 1 always (self-loops)
}

// ---------------- aggregation ----------------
// AGG[i,:] = dinv[i]^2 * X[i,:]   (self-loop term; also zero-inits the buffer)
__global__ void k_agg_init(const float* __restrict__ X, const float* __restrict__ dinv,
                           float* __restrict__ AGG, int n, int D4) {
    int idx = blockIdx.x * blockDim.x + threadIdx.x;
    int node = idx / D4, c = idx % D4;
    if (node >= n) return;
    float s = dinv[node]; s = s * s;
    float4 v = ((const float4*)X)[(size_t)node * D4 + c];
    v.x *= s; v.y *= s; v.z *= s; v.w *= s;
    ((float4*)AGG)[(size_t)node * D4 + c] = v;
}

// One warp per edge: AGG[dst,:] += dinv[src]*dinv[dst] * X[src,:]
__global__ void k_agg_edges(const float* __restrict__ X, float* __restrict__ AGG,
                            const int* __restrict__ src, const int* __restrict__ dst,
                            const float* __restrict__ dinv, int nE, int D4) {
    int e = (blockIdx.x * blockDim.x + threadIdx.x) >> 5;
    if (e >= nE) return;
    int lane = threadIdx.x & 31;
    int s = src[e], d = dst[e];
    float nm = dinv[s] * dinv[d];
    const float4* xs = (const float4*)(X + (size_t)s * (D4 * 4));
    float4* ad = (float4*)(AGG + (size_t)d * (D4 * 4));
    for (int i = lane; i < D4; i += 32) {
        float4 v = xs[i];
        v.x *= nm; v.y *= nm; v.z *= nm; v.w *= nm;
        asm volatile("red.global.add.v4.f32 [%0], {%1,%2,%3,%4};"
                     :: "l"(ad + i), "f"(v.x), "f"(v.y), "f"(v.z), "f"(v.w) : "memory");
    }
}

// ---------------- GEMM + bias + ReLU (C = relu(A*B + bias)) ----------------
// A: MxK row-major, B: KxN row-major, C: MxN row-major. BK divides K, BN divides N.
#define GBM 128
#define GBN 128
#define GBK 16
#define GTM 8
#define GTN 8

__global__ __launch_bounds__(256)
void k_gemm_bias_relu(const float* __restrict__ A, const float* __restrict__ B,
                      const float* __restrict__ bias, float* __restrict__ C,
                      int M, int K, int N) {
    __shared__ float As[GBK][GBM + 4];
    __shared__ float Bs[GBK][GBN];
    int tid = threadIdx.x;
    int rowBase = blockIdx.y * GBM;
    int colBase = blockIdx.x * GBN;

    float acc[GTM][GTN] = {};

    int aRow  = tid >> 2;          // 0..63
    int aCol4 = tid & 3;           // 0..3
    int bRow  = tid >> 5;          // 0..7
    int bCol4 = tid & 31;          // 0..31

    int tr = (tid >> 4) * GTM;
    int tc = (tid & 15) * GTN;

    for (int k0 = 0; k0 < K; k0 += GBK) {
        #pragma unroll
        for (int h = 0; h < 2; h++) {
            int r = aRow + h * 64;
            int gr = rowBase + r;
            float4 v = make_float4(0.f, 0.f, 0.f, 0.f);
            if (gr < M) v = *(const float4*)(A + (size_t)gr * K + k0 + aCol4 * 4);
            As[aCol4 * 4 + 0][r] = v.x;
            As[aCol4 * 4 + 1][r] = v.y;
            As[aCol4 * 4 + 2][r] = v.z;
            As[aCol4 * 4 + 3][r] = v.w;
        }
        #pragma unroll
        for (int h = 0; h < 2; h++) {
            int r = bRow + h * 8;
            float4 v = *(const float4*)(B + (size_t)(k0 + r) * N + colBase + bCol4 * 4);
            *(float4*)&Bs[r][bCol4 * 4] = v;
        }
        __syncthreads();
        #pragma unroll
        for (int k = 0; k < GBK; k++) {
            float ra[GTM], rb[GTN];
            #pragma unroll
            for (int i = 0; i < GTM; i++) ra[i] = As[k][tr + i];
            #pragma unroll
            for (int j = 0; j < GTN; j++) rb[j] = Bs[k][tc + j];
            #pragma unroll
            for (int i = 0; i < GTM; i++)
                #pragma unroll
                for (int j = 0; j < GTN; j++)
                    acc[i][j] += ra[i] * rb[j];
        }
        __syncthreads();
    }

    #pragma unroll
    for (int i = 0; i < GTM; i++) {
        int gr = rowBase + tr + i;
        if (gr >= M) break;
        #pragma unroll
        for (int j = 0; j < GTN; j += 4) {
            int gc = colBase + tc + j;
            float4 v;
            v.x = fmaxf(acc[i][j + 0] + bias[gc + 0], 0.f);
            v.y = fmaxf(acc[i][j + 1] + bias[gc + 1], 0.f);
            v.z = fmaxf(acc[i][j + 2] + bias[gc + 2], 0.f);
            v.w = fmaxf(acc[i][j + 3] + bias[gc + 3], 0.f);
            *(float4*)(C + (size_t)gr * N + gc) = v;
        }
    }
}

// ---------------- pooling ----------------
__global__ void k_zero_pool(float* pool, float* cnt) {
    int i = blockIdx.x * blockDim.x + threadIdx.x;
    if (i < NGRAPH * HID) pool[i] = 0.f;
    if (i < NGRAPH) cnt[i] = 0.f;
}

// one warp per node
__global__ void k_pool_scatter(const float* __restrict__ H, const int* __restrict__ batch,
                               float* __restrict__ pool, float* __restrict__ cnt, int n) {
    int node = (blockIdx.x * blockDim.x + threadIdx.x) >> 5;
    if (node >= n) return;
    int lane = threadIdx.x & 31;
    int g = batch[node];
    const float4* h = (const float4*)(H + (size_t)node * HID);
    float4* pg = (float4*)(pool + (size_t)g * HID);
    #pragma unroll
    for (int i = lane; i < HID / 4; i += 32) {
        float4 v = h[i];
        asm volatile("red.global.add.v4.f32 [%0], {%1,%2,%3,%4};"
                     :: "l"(pg + i), "f"(v.x), "f"(v.y), "f"(v.z), "f"(v.w) : "memory");
    }
    if (lane == 0) atomicAdd(&cnt[g], 1.0f);
}

// ---------------- MLP head: out = relu(pooled@Wf1+bf1)@Wf2 + bf2 ----------------
__global__ void k_mlp(const float* __restrict__ pool, const float* __restrict__ cnt,
                      const float* __restrict__ Wf1, const float* __restrict__ bf1,
                      const float* __restrict__ Wf2, const float* __restrict__ bf2,
                      float* __restrict__ out) {
    int g = blockIdx.x;
    __shared__ float p[HID];
    __shared__ float red[128];
    int t = threadIdx.x;  // 128
    float inv = 1.0f / fmaxf(cnt[g], 1.0f);
    p[t]       = pool[g * HID + t] * inv;
    p[t + 128] = pool[g * HID + 128 + t] * inv;
    __syncthreads();
    float acc = bf1[t];
    #pragma unroll 8
    for (int k = 0; k < HID; k++) acc += p[k] * Wf1[k * 128 + t];
    red[t] = fmaxf(acc, 0.f) * Wf2[t];
    __syncthreads();
    for (int s = 64; s > 0; s >>= 1) {
        if (t < s) red[t] += red[t + s];
        __syncthreads();
    }
    if (t == 0) out[g] = red[0] + bf2[0];
}

// ---------------------------------------------------------------------------
extern "C" void kernel_launch(void* const* d_in, const int* in_sizes, int n_in,
                              void* d_out, int out_size) {
    const float* x   = (const float*)d_in[0];
    const int*   ei  = (const int*)d_in[1];
    const int*   bat = (const int*)d_in[2];
    const float* W1  = (const float*)d_in[3];
    const float* b1  = (const float*)d_in[4];
    const float* W2  = (const float*)d_in[5];
    const float* b2  = (const float*)d_in[6];
    const float* Wf1 = (const float*)d_in[7];
    const float* bf1 = (const float*)d_in[8];
    const float* Wf2 = (const float*)d_in[9];
    const float* bf2 = (const float*)d_in[10];
    float* out = (float*)d_out;

    int n  = in_sizes[0] / 128;   // nodes
    int nE = in_sizes[1] / 2;     // edges
    const int* src = ei;
    const int* dst = ei + nE;

    float *bufA, *bufB, *dinv, *pool, *cnt;
    cudaGetSymbolAddress((void**)&bufA, g_bufA);
    cudaGetSymbolAddress((void**)&bufB, g_bufB);
    cudaGetSymbolAddress((void**)&dinv, g_dinv);
    cudaGetSymbolAddress((void**)&pool, g_pool);
    cudaGetSymbolAddress((void**)&cnt,  g_cnt);

    // --- degrees / norm ---
    k_deg_init<<<(n + 255) / 256, 256>>>(dinv, n);
    k_deg_edges<<<(nE + 255) / 256, 256>>>(dst, dinv, nE);
    k_make_dinv<<<(n + 255) / 256, 256>>>(dinv, n);

    // --- layer 1: agg_x = Â x  (128 dims), then h1 = relu(agg_x @ W1 + b1) ---
    {
        int D4 = 128 / 4;
        long tot = (long)n * D4;
        k_agg_init<<<(unsigned)((tot + 255) / 256), 256>>>(x, dinv, bufA, n, D4);
        long thr = (long)nE * 32;
        k_agg_edges<<<(unsigned)((thr + 255) / 256), 256>>>(x, bufA, src, dst, dinv, nE, D4);
        dim3 grid(256 / GBN, (n + GBM - 1) / GBM);
        k_gemm_bias_relu<<<grid, 256>>>(bufA, W1, b1, bufB, n, 128, 256);
    }

    // --- layer 2: agg_h = Â h1 (256 dims), then h2 = relu(agg_h @ W2 + b2) ---
    {
        int D4 = 256 / 4;
        long tot = (long)n * D4;
        k_agg_init<<<(unsigned)((tot + 255) / 256), 256>>>(bufB, dinv, bufA, n, D4);
        long thr = (long)nE * 32;
        k_agg_edges<<<(unsigned)((thr + 255) / 256), 256>>>(bufB, bufA, src, dst, dinv, nE, D4);
        dim3 grid(256 / GBN, (n + GBM - 1) / GBM);
        k_gemm_bias_relu<<<grid, 256>>>(bufA, W2, b2, bufB, n, 256, 256);
    }

    // --- pooling + MLP head ---
    k_zero_pool<<<(NGRAPH * HID + 255) / 256, 256>>>(pool, cnt);
    {
        long thr = (long)n * 32;
        k_pool_scatter<<<(unsigned)((thr + 255) / 256), 256>>>(bufB, bat, pool, cnt, n);
    }
    k_mlp<<<NGRAPH, 128>>>(pool, cnt, Wf1, bf1, Wf2, bf2, out);
}

// round 3
// speedup vs baseline: 1.2139x; 1.2139x over previous
#include <cuda_runtime.h>
#include <cuda_bf16.h>
#include <cstdint>

// ---------------------------------------------------------------------------
// GCN: h1 = relu((ÂX)W1 + b1); h2 = relu((Âh1)W2 + b2); mean pool; MLP head.
// GEMMs via mma.sync bf16 (HMMA) with 3xBF16 split precision.
// ---------------------------------------------------------------------------

#define MAX_NODES 100000
#define HID 256
#define NGRAPH 2048

__device__ float g_bufA[(size_t)MAX_NODES * HID];
__device__ float g_bufB[(size_t)MAX_NODES * HID];
__device__ float g_dinv[MAX_NODES];
__device__ float g_pool[NGRAPH * HID];
__device__ float g_cnt[NGRAPH];
__device__ __nv_bfloat16 g_Whi[256 * 256];   // W^T hi  [N][K]
__device__ __nv_bfloat16 g_Wlo[256 * 256];   // W^T lo  [N][K]

// ========================= helpers =========================
__device__ __forceinline__ void split1(float a, __nv_bfloat16& hi, __nv_bfloat16& lo) {
    hi = __float2bfloat16_rn(a);
    lo = __float2bfloat16_rn(a - __bfloat162float(hi));
}

#define LDMX4(R, ADDR)                                                          \
    asm volatile("ldmatrix.sync.aligned.m8n8.x4.shared.b16 {%0,%1,%2,%3}, [%4];" \
                 : "=r"((R)[0]), "=r"((R)[1]), "=r"((R)[2]), "=r"((R)[3])        \
                 : "r"(ADDR))

#define MMA16816(D, A, B0, B1)                                                  \
    asm volatile("mma.sync.aligned.m16n8k16.row.col.f32.bf16.bf16.f32 "          \
                 "{%0,%1,%2,%3}, {%4,%5,%6,%7}, {%8,%9}, {%0,%1,%2,%3};"         \
                 : "+f"((D)[0]), "+f"((D)[1]), "+f"((D)[2]), "+f"((D)[3])        \
                 : "r"((A)[0]), "r"((A)[1]), "r"((A)[2]), "r"((A)[3]),           \
                   "r"(B0), "r"(B1))

// ================= W prep: fp32 [K][256] -> bf16 hi/lo [256][K] =============
__global__ void k_prep_W(const float* __restrict__ W,
                         __nv_bfloat16* __restrict__ Whi,
                         __nv_bfloat16* __restrict__ Wlo, int K) {
    int idx = blockIdx.x * blockDim.x + threadIdx.x;
    if (idx >= K * 256) return;
    int n = idx / K, k = idx % K;
    float v = W[(size_t)k * 256 + n];
    __nv_bfloat16 hi, lo;
    split1(v, hi, lo);
    Whi[idx] = hi;
    Wlo[idx] = lo;
}

// ===================== tensor-core GEMM (M x K) @ (K x 256) =================
// C = relu(A @ W + bias); W given pre-transposed as bf16 hi/lo [256][K].
#define BM 128
#define BN 128
#define BK 32
#define LDS_PAD 40   // bf16 elems per smem row (32 + 8 pad) -> conflict-free ldmatrix

__global__ __launch_bounds__(256, 2)
void k_gemm_mma(const float* __restrict__ A,
                const __nv_bfloat16* __restrict__ Bhi,
                const __nv_bfloat16* __restrict__ Blo,
                const float* __restrict__ bias, float* __restrict__ C,
                int M, int K) {
    __shared__ __align__(16) __nv_bfloat16 sAh[BM * LDS_PAD];
    __shared__ __align__(16) __nv_bfloat16 sAl[BM * LDS_PAD];
    __shared__ __align__(16) __nv_bfloat16 sBh[BN * LDS_PAD];
    __shared__ __align__(16) __nv_bfloat16 sBl[BN * LDS_PAD];

    const int tid = threadIdx.x;
    const int wid = tid >> 5, lane = tid & 31;
    const int warpM = wid & 3;        // 4 warps along M (32 rows each)
    const int warpN = wid >> 2;       // 2 warps along N (64 cols each)
    const int rowBase = blockIdx.y * BM;
    const int colBase = blockIdx.x * BN;

    float acc[2][8][4];
    #pragma unroll
    for (int i = 0; i < 2; i++)
        #pragma unroll
        for (int j = 0; j < 8; j++)
            #pragma unroll
            for (int q = 0; q < 4; q++) acc[i][j][q] = 0.f;

    // ldmatrix lane addressing (elements)
    const int aRow = warpM * 32 + (lane & 15);
    const int aK   = (lane >> 4) * 8;
    const int bRowBase = warpN * 64 + (lane & 7) + ((lane >> 4) << 3);
    const int bK   = ((lane >> 3) & 1) * 8;

    uint32_t sAh_b = (uint32_t)__cvta_generic_to_shared(sAh);
    uint32_t sAl_b = (uint32_t)__cvta_generic_to_shared(sAl);
    uint32_t sBh_b = (uint32_t)__cvta_generic_to_shared(sBh);
    uint32_t sBl_b = (uint32_t)__cvta_generic_to_shared(sBl);

    for (int k0 = 0; k0 < K; k0 += BK) {
        // ---- load A tile 128x32 fp32 -> hi/lo bf16 ----
        {
            int r0 = tid >> 3;              // 0..31
            int k4 = (tid & 7) * 4;         // 0..28 step 4
            #pragma unroll
            for (int it = 0; it < 4; ++it) {
                int r = r0 + it * 32;
                int gr = rowBase + r;
                float4 v = make_float4(0.f, 0.f, 0.f, 0.f);
                if (gr < M) v = *(const float4*)(A + (size_t)gr * K + k0 + k4);
                __nv_bfloat16 h0, l0, h1, l1, h2, l2, h3, l3;
                split1(v.x, h0, l0); split1(v.y, h1, l1);
                split1(v.z, h2, l2); split1(v.w, h3, l3);
                __nv_bfloat162 H0 = __nv_bfloat162(h0, h1), H1 = __nv_bfloat162(h2, h3);
                __nv_bfloat162 L0 = __nv_bfloat162(l0, l1), L1 = __nv_bfloat162(l2, l3);
                int off = r * LDS_PAD + k4;
                *(uint2*)&sAh[off] = make_uint2(*(uint32_t*)&H0, *(uint32_t*)&H1);
                *(uint2*)&sAl[off] = make_uint2(*(uint32_t*)&L0, *(uint32_t*)&L1);
            }
        }
        // ---- load B tile 128x32 bf16 hi/lo (already [n][k]) ----
        {
            #pragma unroll
            for (int it = 0; it < 2; ++it) {
                int i = tid + it * 256;
                int n = i >> 2;
                int kq = (i & 3) * 8;
                int off = n * LDS_PAD + kq;
                const size_t g = (size_t)(colBase + n) * K + k0 + kq;
                *(uint4*)&sBh[off] = *(const uint4*)(Bhi + g);
                *(uint4*)&sBl[off] = *(const uint4*)(Blo + g);
            }
        }
        __syncthreads();

        #pragma unroll
        for (int kk = 0; kk < BK; kk += 16) {
            uint32_t aH[2][4], aL[2][4];
            #pragma unroll
            for (int mi = 0; mi < 2; ++mi) {
                uint32_t o = (uint32_t)((aRow + mi * 16) * LDS_PAD + kk + aK) * 2;
                LDMX4(aH[mi], sAh_b + o);
                LDMX4(aL[mi], sAl_b + o);
            }
            #pragma unroll
            for (int nj = 0; nj < 4; ++nj) {
                uint32_t bH[4], bL[4];
                uint32_t o = (uint32_t)((bRowBase + nj * 16) * LDS_PAD + kk + bK) * 2;
                LDMX4(bH, sBh_b + o);
                LDMX4(bL, sBl_b + o);
                #pragma unroll
                for (int mi = 0; mi < 2; ++mi) {
                    MMA16816(acc[mi][nj * 2 + 0], aH[mi], bH[0], bH[1]);
                    MMA16816(acc[mi][nj * 2 + 1], aH[mi], bH[2], bH[3]);
                    MMA16816(acc[mi][nj * 2 + 0], aH[mi], bL[0], bL[1]);
                    MMA16816(acc[mi][nj * 2 + 1], aH[mi], bL[2], bL[3]);
                    MMA16816(acc[mi][nj * 2 + 0], aL[mi], bH[0], bH[1]);
                    MMA16816(acc[mi][nj * 2 + 1], aL[mi], bH[2], bH[3]);
                }
            }
        }
        __syncthreads();
    }

    // ---- epilogue: bias + relu ----
    const int erow = rowBase + warpM * 32 + (lane >> 2);
    const int ecol = colBase + warpN * 64 + (lane & 3) * 2;
    #pragma unroll
    for (int mi = 0; mi < 2; ++mi) {
        int r0 = erow + mi * 16;
        #pragma unroll
        for (int nj = 0; nj < 8; ++nj) {
            int c = ecol + nj * 8;
            float b0 = bias[c], b1 = bias[c + 1];
            if (r0 < M) {
                float2 v;
                v.x = fmaxf(acc[mi][nj][0] + b0, 0.f);
                v.y = fmaxf(acc[mi][nj][1] + b1, 0.f);
                *(float2*)(C + (size_t)r0 * 256 + c) = v;
            }
            if (r0 + 8 < M) {
                float2 v;
                v.x = fmaxf(acc[mi][nj][2] + b0, 0.f);
                v.y = fmaxf(acc[mi][nj][3] + b1, 0.f);
                *(float2*)(C + (size_t)(r0 + 8) * 256 + c) = v;
            }
        }
    }
}

// ======================= degree / normalization ============================
__global__ void k_deg_init(float* deg, int n) {
    int i = blockIdx.x * blockDim.x + threadIdx.x;
    if (i < n) deg[i] = 1.0f;
}
__global__ void k_deg_edges(const int* __restrict__ dst, float* __restrict__ deg, int nE) {
    int i = blockIdx.x * blockDim.x + threadIdx.x;
    if (i < nE) atomicAdd(&deg[dst[i]], 1.0f);
}
__global__ void k_make_dinv(float* deg, int n) {
    int i = blockIdx.x * blockDim.x + threadIdx.x;
    if (i < n) deg[i] = rsqrtf(deg[i]);
}

// ============================ aggregation ==================================
__global__ void k_agg_init(const float* __restrict__ X, const float* __restrict__ dinv,
                           float* __restrict__ AGG, int n, int D4) {
    int idx = blockIdx.x * blockDim.x + threadIdx.x;
    int node = idx / D4, c = idx % D4;
    if (node >= n) return;
    float s = dinv[node]; s = s * s;
    float4 v = ((const float4*)X)[(size_t)node * D4 + c];
    v.x *= s; v.y *= s; v.z *= s; v.w *= s;
    ((float4*)AGG)[(size_t)node * D4 + c] = v;
}

__global__ void k_agg_edges(const float* __restrict__ X, float* __restrict__ AGG,
                            const int* __restrict__ src, const int* __restrict__ dst,
                            const float* __restrict__ dinv, int nE, int D4) {
    int e = (blockIdx.x * blockDim.x + threadIdx.x) >> 5;
    if (e >= nE) return;
    int lane = threadIdx.x & 31;
    int s = src[e], d = dst[e];
    float nm = dinv[s] * dinv[d];
    const float4* xs = (const float4*)(X + (size_t)s * (D4 * 4));
    float4* ad = (float4*)(AGG + (size_t)d * (D4 * 4));
    for (int i = lane; i < D4; i += 32) {
        float4 v = xs[i];
        v.x *= nm; v.y *= nm; v.z *= nm; v.w *= nm;
        asm volatile("red.global.add.v4.f32 [%0], {%1,%2,%3,%4};"
                     :: "l"(ad + i), "f"(v.x), "f"(v.y), "f"(v.z), "f"(v.w) : "memory");
    }
}

// ============================== pooling ====================================
__global__ void k_zero_pool(float* pool, float* cnt) {
    int i = blockIdx.x * blockDim.x + threadIdx.x;
    if (i < NGRAPH * HID) pool[i] = 0.f;
    if (i < NGRAPH) cnt[i] = 0.f;
}
__global__ void k_pool_scatter(const float* __restrict__ H, const int* __restrict__ batch,
                               float* __restrict__ pool, float* __restrict__ cnt, int n) {
    int node = (blockIdx.x * blockDim.x + threadIdx.x) >> 5;
    if (node >= n) return;
    int lane = threadIdx.x & 31;
    int g = batch[node];
    const float4* h = (const float4*)(H + (size_t)node * HID);
    float4* pg = (float4*)(pool + (size_t)g * HID);
    #pragma unroll
    for (int i = lane; i < HID / 4; i += 32) {
        float4 v = h[i];
        asm volatile("red.global.add.v4.f32 [%0], {%1,%2,%3,%4};"
                     :: "l"(pg + i), "f"(v.x), "f"(v.y), "f"(v.z), "f"(v.w) : "memory");
    }
    if (lane == 0) atomicAdd(&cnt[g], 1.0f);
}

// ================================ MLP head =================================
__global__ void k_mlp(const float* __restrict__ pool, const float* __restrict__ cnt,
                      const float* __restrict__ Wf1, const float* __restrict__ bf1,
                      const float* __restrict__ Wf2, const float* __restrict__ bf2,
                      float* __restrict__ out) {
    int g = blockIdx.x;
    __shared__ float p[HID];
    __shared__ float red[128];
    int t = threadIdx.x;
    float inv = 1.0f / fmaxf(cnt[g], 1.0f);
    p[t]       = pool[g * HID + t] * inv;
    p[t + 128] = pool[g * HID + 128 + t] * inv;
    __syncthreads();
    float acc = bf1[t];
    #pragma unroll 8
    for (int k = 0; k < HID; k++) acc += p[k] * Wf1[k * 128 + t];
    red[t] = fmaxf(acc, 0.f) * Wf2[t];
    __syncthreads();
    for (int s = 64; s > 0; s >>= 1) {
        if (t < s) red[t] += red[t + s];
        __syncthreads();
    }
    if (t == 0) out[g] = red[0] + bf2[0];
}

// ---------------------------------------------------------------------------
extern "C" void kernel_launch(void* const* d_in, const int* in_sizes, int n_in,
                              void* d_out, int out_size) {
    const float* x   = (const float*)d_in[0];
    const int*   ei  = (const int*)d_in[1];
    const int*   bat = (const int*)d_in[2];
    const float* W1  = (const float*)d_in[3];
    const float* b1  = (const float*)d_in[4];
    const float* W2  = (const float*)d_in[5];
    const float* b2  = (const float*)d_in[6];
    const float* Wf1 = (const float*)d_in[7];
    const float* bf1 = (const float*)d_in[8];
    const float* Wf2 = (const float*)d_in[9];
    const float* bf2 = (const float*)d_in[10];
    float* out = (float*)d_out;

    int n  = in_sizes[0] / 128;
    int nE = in_sizes[1] / 2;
    const int* src = ei;
    const int* dst = ei + nE;

    float *bufA, *bufB, *dinv, *pool, *cnt;
    __nv_bfloat16 *Whi, *Wlo;
    cudaGetSymbolAddress((void**)&bufA, g_bufA);
    cudaGetSymbolAddress((void**)&bufB, g_bufB);
    cudaGetSymbolAddress((void**)&dinv, g_dinv);
    cudaGetSymbolAddress((void**)&pool, g_pool);
    cudaGetSymbolAddress((void**)&cnt,  g_cnt);
    cudaGetSymbolAddress((void**)&Whi,  g_Whi);
    cudaGetSymbolAddress((void**)&Wlo,  g_Wlo);

    // --- degrees / norm ---
    k_deg_init<<<(n + 255) / 256, 256>>>(dinv, n);
    k_deg_edges<<<(nE + 255) / 256, 256>>>(dst, dinv, nE);
    k_make_dinv<<<(n + 255) / 256, 256>>>(dinv, n);

    dim3 gemmGrid(2, (n + BM - 1) / BM);

    // --- layer 1: agg_x = Â x (128 dims); h1 = relu(agg_x @ W1 + b1) ---
    {
        int D4 = 128 / 4;
        long tot = (long)n * D4;
        k_agg_init<<<(unsigned)((tot + 255) / 256), 256>>>(x, dinv, bufA, n, D4);
        long thr = (long)nE * 32;
        k_agg_edges<<<(unsigned)((thr + 255) / 256), 256>>>(x, bufA, src, dst, dinv, nE, D4);
        k_prep_W<<<(128 * 256 + 255) / 256, 256>>>(W1, Whi, Wlo, 128);
        k_gemm_mma<<<gemmGrid, 256>>>(bufA, Whi, Wlo, b1, bufB, n, 128);
    }

    // --- layer 2: agg_h = Â h1 (256 dims); h2 = relu(agg_h @ W2 + b2) ---
    {
        int D4 = 256 / 4;
        long tot = (long)n * D4;
        k_agg_init<<<(unsigned)((tot + 255) / 256), 256>>>(bufB, dinv, bufA, n, D4);
        long thr = (long)nE * 32;
        k_agg_edges<<<(unsigned)((thr + 255) / 256), 256>>>(bufB, bufA, src, dst, dinv, nE, D4);
        k_prep_W<<<(256 * 256 + 255) / 256, 256>>>(W2, Whi, Wlo, 256);
        k_gemm_mma<<<gemmGrid, 256>>>(bufA, Whi, Wlo, b2, bufB, n, 256);
    }

    // --- pooling + MLP head ---
    k_zero_pool<<<(NGRAPH * HID + 255) / 256, 256>>>(pool, cnt);
    {
        long thr = (long)n * 32;
        k_pool_scatter<<<(unsigned)((thr + 255) / 256), 256>>>(bufB, bat, pool, cnt, n);
    }
    k_mlp<<<NGRAPH, 128>>>(pool, cnt, Wf1, bf1, Wf2, bf2, out);
}

// round 4
// speedup vs baseline: 2.2927x; 1.8887x over previous
#include <cuda_runtime.h>
#include <cuda_bf16.h>
#include <cstdint>

// ---------------------------------------------------------------------------
// GCN: h1 = relu((ÂX)W1 + b1); h2 = relu((Âh1)W2 + b2); mean pool; MLP head.
// Edge aggregation via CSR gather (atomic-free). GEMMs via bf16 HMMA, 3xBF16.
// ---------------------------------------------------------------------------

#define MAX_NODES 100000
#define MAX_EDGES 1700000
#define HID 256
#define NGRAPH 2048

__device__ float g_bufA[(size_t)MAX_NODES * HID];
__device__ float g_bufB[(size_t)MAX_NODES * HID];
__device__ float g_dinv[MAX_NODES];
__device__ float g_pool[NGRAPH * HID];
__device__ float g_cnt[NGRAPH];
__device__ __nv_bfloat16 g_Whi[256 * 256];
__device__ __nv_bfloat16 g_Wlo[256 * 256];
__device__ int   g_cntI[MAX_NODES];
__device__ int   g_rowptr[MAX_NODES + 1];
__device__ int   g_cursor[MAX_NODES];
__device__ int   g_csrc[MAX_EDGES];
__device__ float g_cnorm[MAX_EDGES];

// ========================= helpers =========================
__device__ __forceinline__ void split1(float a, __nv_bfloat16& hi, __nv_bfloat16& lo) {
    hi = __float2bfloat16_rn(a);
    lo = __float2bfloat16_rn(a - __bfloat162float(hi));
}

#define LDMX4(R, ADDR)                                                          \
    asm volatile("ldmatrix.sync.aligned.m8n8.x4.shared.b16 {%0,%1,%2,%3}, [%4];" \
                 : "=r"((R)[0]), "=r"((R)[1]), "=r"((R)[2]), "=r"((R)[3])        \
                 : "r"(ADDR))

#define MMA16816(D, A, B0, B1)                                                  \
    asm volatile("mma.sync.aligned.m16n8k16.row.col.f32.bf16.bf16.f32 "          \
                 "{%0,%1,%2,%3}, {%4,%5,%6,%7}, {%8,%9}, {%0,%1,%2,%3};"         \
                 : "+f"((D)[0]), "+f"((D)[1]), "+f"((D)[2]), "+f"((D)[3])        \
                 : "r"((A)[0]), "r"((A)[1]), "r"((A)[2]), "r"((A)[3]),           \
                   "r"(B0), "r"(B1))

// ===================== CSR construction =====================
__global__ void k_zero_cnt(int* cnt, int n) {
    int i = blockIdx.x * blockDim.x + threadIdx.x;
    if (i < n) cnt[i] = 0;
}
__global__ void k_count(const int* __restrict__ dst, int* __restrict__ cnt, int nE) {
    int i = blockIdx.x * blockDim.x + threadIdx.x;
    if (i < nE) atomicAdd(&cnt[dst[i]], 1);
}
__global__ void k_dinv(const int* __restrict__ cnt, float* __restrict__ dinv, int n) {
    int i = blockIdx.x * blockDim.x + threadIdx.x;
    if (i < n) dinv[i] = rsqrtf((float)(cnt[i] + 1));
}
// single-block exclusive scan (1024 threads, serial chunks)
__global__ void k_scan(const int* __restrict__ cnt, int* __restrict__ rowptr,
                       int* __restrict__ cursor, int n) {
    __shared__ int s[1024];
    int t = threadIdx.x;
    int chunk = (n + 1023) / 1024;
    int beg = t * chunk;
    int end = min(beg + chunk, n);
    int sum = 0;
    for (int i = beg; i < end; ++i) sum += cnt[i];
    s[t] = sum;
    __syncthreads();
    #pragma unroll
    for (int off = 1; off < 1024; off <<= 1) {
        int v = (t >= off) ? s[t - off] : 0;
        __syncthreads();
        if (t >= off) s[t] += v;
        __syncthreads();
    }
    int run = s[t] - sum;      // exclusive prefix
    for (int i = beg; i < end; ++i) {
        rowptr[i] = run;
        cursor[i] = run;
        run += cnt[i];
    }
    if (beg < n && end == n) rowptr[n] = run;
}
__global__ void k_fill(const int* __restrict__ src, const int* __restrict__ dst,
                       const float* __restrict__ dinv, int* __restrict__ cursor,
                       int* __restrict__ csrc, float* __restrict__ cnorm, int nE) {
    int i = blockIdx.x * blockDim.x + threadIdx.x;
    if (i >= nE) return;
    int s = src[i], d = dst[i];
    int pos = atomicAdd(&cursor[d], 1);
    csrc[pos] = s;
    cnorm[pos] = dinv[s] * dinv[d];
}

// ===================== CSR gather aggregation =====================
// OUT[i,:] = dinv[i]^2 * X[i,:] + sum_e norm_e * X[src_e,:]
__global__ __launch_bounds__(256)
void k_gather128(const float* __restrict__ X, const int* __restrict__ rowptr,
                 const int* __restrict__ csrc, const float* __restrict__ cnorm,
                 const float* __restrict__ dinv, float* __restrict__ OUT, int n) {
    int node = (blockIdx.x * blockDim.x + threadIdx.x) >> 5;
    if (node >= n) return;
    int lane = threadIdx.x & 31;
    float di = dinv[node];
    const float4* Xv = (const float4*)X;
    float4 a = Xv[(size_t)node * 32 + lane];
    float s2 = di * di;
    a.x *= s2; a.y *= s2; a.z *= s2; a.w *= s2;
    int e = rowptr[node], e1 = rowptr[node + 1];
    for (; e + 2 <= e1; e += 2) {
        int   s0 = csrc[e],     s1 = csrc[e + 1];
        float n0 = cnorm[e],    n1 = cnorm[e + 1];
        float4 v0 = Xv[(size_t)s0 * 32 + lane];
        float4 v1 = Xv[(size_t)s1 * 32 + lane];
        a.x += n0 * v0.x + n1 * v1.x;
        a.y += n0 * v0.y + n1 * v1.y;
        a.z += n0 * v0.z + n1 * v1.z;
        a.w += n0 * v0.w + n1 * v1.w;
    }
    if (e < e1) {
        int s0 = csrc[e]; float n0 = cnorm[e];
        float4 v0 = Xv[(size_t)s0 * 32 + lane];
        a.x += n0 * v0.x; a.y += n0 * v0.y; a.z += n0 * v0.z; a.w += n0 * v0.w;
    }
    ((float4*)OUT)[(size_t)node * 32 + lane] = a;
}

__global__ __launch_bounds__(256)
void k_gather256(const float* __restrict__ X, const int* __restrict__ rowptr,
                 const int* __restrict__ csrc, const float* __restrict__ cnorm,
                 const float* __restrict__ dinv, float* __restrict__ OUT, int n) {
    int node = (blockIdx.x * blockDim.x + threadIdx.x) >> 5;
    if (node >= n) return;
    int lane = threadIdx.x & 31;
    float di = dinv[node];
    const float4* Xv = (const float4*)X;
    size_t base = (size_t)node * 64 + lane;
    float4 a0 = Xv[base], a1 = Xv[base + 32];
    float s2 = di * di;
    a0.x *= s2; a0.y *= s2; a0.z *= s2; a0.w *= s2;
    a1.x *= s2; a1.y *= s2; a1.z *= s2; a1.w *= s2;
    int e = rowptr[node], e1 = rowptr[node + 1];
    for (; e < e1; ++e) {
        int s = csrc[e]; float nm = cnorm[e];
        size_t sb = (size_t)s * 64 + lane;
        float4 v0 = Xv[sb], v1 = Xv[sb + 32];
        a0.x += nm * v0.x; a0.y += nm * v0.y; a0.z += nm * v0.z; a0.w += nm * v0.w;
        a1.x += nm * v1.x; a1.y += nm * v1.y; a1.z += nm * v1.z; a1.w += nm * v1.w;
    }
    ((float4*)OUT)[base] = a0;
    ((float4*)OUT)[base + 32] = a1;
}

// ================= W prep: fp32 [K][256] -> bf16 hi/lo [256][K] =============
__global__ void k_prep_W(const float* __restrict__ W,
                         __nv_bfloat16* __restrict__ Whi,
                         __nv_bfloat16* __restrict__ Wlo, int K) {
    int idx = blockIdx.x * blockDim.x + threadIdx.x;
    if (idx >= K * 256) return;
    int n = idx / K, k = idx % K;
    float v = W[(size_t)k * 256 + n];
    __nv_bfloat16 hi, lo;
    split1(v, hi, lo);
    Whi[idx] = hi;
    Wlo[idx] = lo;
}

// ===================== tensor-core GEMM (M x K) @ (K x 256) =================
#define BM 128
#define BN 128
#define BK 32
#define LDS_PAD 40

__global__ __launch_bounds__(256, 2)
void k_gemm_mma(const float* __restrict__ A,
                const __nv_bfloat16* __restrict__ Bhi,
                const __nv_bfloat16* __restrict__ Blo,
                const float* __restrict__ bias, float* __restrict__ C,
                int M, int K) {
    __shared__ __align__(16) __nv_bfloat16 sAh[BM * LDS_PAD];
    __shared__ __align__(16) __nv_bfloat16 sAl[BM * LDS_PAD];
    __shared__ __align__(16) __nv_bfloat16 sBh[BN * LDS_PAD];
    __shared__ __align__(16) __nv_bfloat16 sBl[BN * LDS_PAD];

    const int tid = threadIdx.x;
    const int wid = tid >> 5, lane = tid & 31;
    const int warpM = wid & 3;
    const int warpN = wid >> 2;
    const int rowBase = blockIdx.y * BM;
    const int colBase = blockIdx.x * BN;

    float acc[2][8][4];
    #pragma unroll
    for (int i = 0; i < 2; i++)
        #pragma unroll
        for (int j = 0; j < 8; j++)
            #pragma unroll
            for (int q = 0; q < 4; q++) acc[i][j][q] = 0.f;

    const int aRow = warpM * 32 + (lane & 15);
    const int aK   = (lane >> 4) * 8;
    const int bRowBase = warpN * 64 + (lane & 7) + ((lane >> 4) << 3);
    const int bK   = ((lane >> 3) & 1) * 8;

    uint32_t sAh_b = (uint32_t)__cvta_generic_to_shared(sAh);
    uint32_t sAl_b = (uint32_t)__cvta_generic_to_shared(sAl);
    uint32_t sBh_b = (uint32_t)__cvta_generic_to_shared(sBh);
    uint32_t sBl_b = (uint32_t)__cvta_generic_to_shared(sBl);

    for (int k0 = 0; k0 < K; k0 += BK) {
        {
            int r0 = tid >> 3;
            int k4 = (tid & 7) * 4;
            #pragma unroll
            for (int it = 0; it < 4; ++it) {
                int r = r0 + it * 32;
                int gr = rowBase + r;
                float4 v = make_float4(0.f, 0.f, 0.f, 0.f);
                if (gr < M) v = *(const float4*)(A + (size_t)gr * K + k0 + k4);
                __nv_bfloat16 h0, l0, h1, l1, h2, l2, h3, l3;
                split1(v.x, h0, l0); split1(v.y, h1, l1);
                split1(v.z, h2, l2); split1(v.w, h3, l3);
                __nv_bfloat162 H0 = __nv_bfloat162(h0, h1), H1 = __nv_bfloat162(h2, h3);
                __nv_bfloat162 L0 = __nv_bfloat162(l0, l1), L1 = __nv_bfloat162(l2, l3);
                int off = r * LDS_PAD + k4;
                *(uint2*)&sAh[off] = make_uint2(*(uint32_t*)&H0, *(uint32_t*)&H1);
                *(uint2*)&sAl[off] = make_uint2(*(uint32_t*)&L0, *(uint32_t*)&L1);
            }
        }
        {
            #pragma unroll
            for (int it = 0; it < 2; ++it) {
                int i = tid + it * 256;
                int n = i >> 2;
                int kq = (i & 3) * 8;
                int off = n * LDS_PAD + kq;
                const size_t g = (size_t)(colBase + n) * K + k0 + kq;
                *(uint4*)&sBh[off] = *(const uint4*)(Bhi + g);
                *(uint4*)&sBl[off] = *(const uint4*)(Blo + g);
            }
        }
        __syncthreads();

        #pragma unroll
        for (int kk = 0; kk < BK; kk += 16) {
            uint32_t aH[2][4], aL[2][4];
            #pragma unroll
            for (int mi = 0; mi < 2; ++mi) {
                uint32_t o = (uint32_t)((aRow + mi * 16) * LDS_PAD + kk + aK) * 2;
                LDMX4(aH[mi], sAh_b + o);
                LDMX4(aL[mi], sAl_b + o);
            }
            #pragma unroll
            for (int nj = 0; nj < 4; ++nj) {
                uint32_t bH[4], bL[4];
                uint32_t o = (uint32_t)((bRowBase + nj * 16) * LDS_PAD + kk + bK) * 2;
                LDMX4(bH, sBh_b + o);
                LDMX4(bL, sBl_b + o);
                #pragma unroll
                for (int mi = 0; mi < 2; ++mi) {
                    MMA16816(acc[mi][nj * 2 + 0], aH[mi], bH[0], bH[1]);
                    MMA16816(acc[mi][nj * 2 + 1], aH[mi], bH[2], bH[3]);
                    MMA16816(acc[mi][nj * 2 + 0], aH[mi], bL[0], bL[1]);
                    MMA16816(acc[mi][nj * 2 + 1], aH[mi], bL[2], bL[3]);
                    MMA16816(acc[mi][nj * 2 + 0], aL[mi], bH[0], bH[1]);
                    MMA16816(acc[mi][nj * 2 + 1], aL[mi], bH[2], bH[3]);
                }
            }
        }
        __syncthreads();
    }

    const int erow = rowBase + warpM * 32 + (lane >> 2);
    const int ecol = colBase + warpN * 64 + (lane & 3) * 2;
    #pragma unroll
    for (int mi = 0; mi < 2; ++mi) {
        int r0 = erow + mi * 16;
        #pragma unroll
        for (int nj = 0; nj < 8; ++nj) {
            int c = ecol + nj * 8;
            float b0 = bias[c], b1 = bias[c + 1];
            if (r0 < M) {
                float2 v;
                v.x = fmaxf(acc[mi][nj][0] + b0, 0.f);
                v.y = fmaxf(acc[mi][nj][1] + b1, 0.f);
                *(float2*)(C + (size_t)r0 * 256 + c) = v;
            }
            if (r0 + 8 < M) {
                float2 v;
                v.x = fmaxf(acc[mi][nj][2] + b0, 0.f);
                v.y = fmaxf(acc[mi][nj][3] + b1, 0.f);
                *(float2*)(C + (size_t)(r0 + 8) * 256 + c) = v;
            }
        }
    }
}

// ============================== pooling ====================================
__global__ void k_zero_pool(float* pool, float* cnt) {
    int i = blockIdx.x * blockDim.x + threadIdx.x;
    if (i < NGRAPH * HID) pool[i] = 0.f;
    if (i < NGRAPH) cnt[i] = 0.f;
}
__global__ void k_pool_scatter(const float* __restrict__ H, const int* __restrict__ batch,
                               float* __restrict__ pool, float* __restrict__ cnt, int n) {
    int node = (blockIdx.x * blockDim.x + threadIdx.x) >> 5;
    if (node >= n) return;
    int lane = threadIdx.x & 31;
    int g = batch[node];
    const float4* h = (const float4*)(H + (size_t)node * HID);
    float4* pg = (float4*)(pool + (size_t)g * HID);
    #pragma unroll
    for (int i = lane; i < HID / 4; i += 32) {
        float4 v = h[i];
        asm volatile("red.global.add.v4.f32 [%0], {%1,%2,%3,%4};"
                     :: "l"(pg + i), "f"(v.x), "f"(v.y), "f"(v.z), "f"(v.w) : "memory");
    }
    if (lane == 0) atomicAdd(&cnt[g], 1.0f);
}

// ================================ MLP head =================================
__global__ void k_mlp(const float* __restrict__ pool, const float* __restrict__ cnt,
                      const float* __restrict__ Wf1, const float* __restrict__ bf1,
                      const float* __restrict__ Wf2, const float* __restrict__ bf2,
                      float* __restrict__ out) {
    int g = blockIdx.x;
    __shared__ float p[HID];
    __shared__ float red[128];
    int t = threadIdx.x;
    float inv = 1.0f / fmaxf(cnt[g], 1.0f);
    p[t]       = pool[g * HID + t] * inv;
    p[t + 128] = pool[g * HID + 128 + t] * inv;
    __syncthreads();
    float acc = bf1[t];
    #pragma unroll 8
    for (int k = 0; k < HID; k++) acc += p[k] * Wf1[k * 128 + t];
    red[t] = fmaxf(acc, 0.f) * Wf2[t];
    __syncthreads();
    for (int s = 64; s > 0; s >>= 1) {
        if (t < s) red[t] += red[t + s];
        __syncthreads();
    }
    if (t == 0) out[g] = red[0] + bf2[0];
}

// ---------------------------------------------------------------------------
extern "C" void kernel_launch(void* const* d_in, const int* in_sizes, int n_in,
                              void* d_out, int out_size) {
    const float* x   = (const float*)d_in[0];
    const int*   ei  = (const int*)d_in[1];
    const int*   bat = (const int*)d_in[2];
    const float* W1  = (const float*)d_in[3];
    const float* b1  = (const float*)d_in[4];
    const float* W2  = (const float*)d_in[5];
    const float* b2  = (const float*)d_in[6];
    const float* Wf1 = (const float*)d_in[7];
    const float* bf1 = (const float*)d_in[8];
    const float* Wf2 = (const float*)d_in[9];
    const float* bf2 = (const float*)d_in[10];
    float* out = (float*)d_out;

    int n  = in_sizes[0] / 128;
    int nE = in_sizes[1] / 2;
    const int* src = ei;
    const int* dst = ei + nE;

    float *bufA, *bufB, *dinv, *pool, *cnt;
    __nv_bfloat16 *Whi, *Wlo;
    int *cntI, *rowptr, *cursor, *csrc;
    float *cnorm;
    cudaGetSymbolAddress((void**)&bufA, g_bufA);
    cudaGetSymbolAddress((void**)&bufB, g_bufB);
    cudaGetSymbolAddress((void**)&dinv, g_dinv);
    cudaGetSymbolAddress((void**)&pool, g_pool);
    cudaGetSymbolAddress((void**)&cnt,  g_cnt);
    cudaGetSymbolAddress((void**)&Whi,  g_Whi);
    cudaGetSymbolAddress((void**)&Wlo,  g_Wlo);
    cudaGetSymbolAddress((void**)&cntI, g_cntI);
    cudaGetSymbolAddress((void**)&rowptr, g_rowptr);
    cudaGetSymbolAddress((void**)&cursor, g_cursor);
    cudaGetSymbolAddress((void**)&csrc, g_csrc);
    cudaGetSymbolAddress((void**)&cnorm, g_cnorm);

    // --- CSR build ---
    k_zero_cnt<<<(n + 255) / 256, 256>>>(cntI, n);
    k_count<<<(nE + 255) / 256, 256>>>(dst, cntI, nE);
    k_dinv<<<(n + 255) / 256, 256>>>(cntI, dinv, n);
    k_scan<<<1, 1024>>>(cntI, rowptr, cursor, n);
    k_fill<<<(nE + 255) / 256, 256>>>(src, dst, dinv, cursor, csrc, cnorm, nE);

    dim3 gemmGrid(2, (n + BM - 1) / BM);
    unsigned gatherBlocks = (unsigned)(((long)n * 32 + 255) / 256);

    // --- layer 1 ---
    k_gather128<<<gatherBlocks, 256>>>(x, rowptr, csrc, cnorm, dinv, bufA, n);
    k_prep_W<<<(128 * 256 + 255) / 256, 256>>>(W1, Whi, Wlo, 128);
    k_gemm_mma<<<gemmGrid, 256>>>(bufA, Whi, Wlo, b1, bufB, n, 128);

    // --- layer 2 ---
    k_gather256<<<gatherBlocks, 256>>>(bufB, rowptr, csrc, cnorm, dinv, bufA, n);
    k_prep_W<<<(256 * 256 + 255) / 256, 256>>>(W2, Whi, Wlo, 256);
    k_gemm_mma<<<gemmGrid, 256>>>(bufA, Whi, Wlo, b2, bufB, n, 256);

    // --- pooling + MLP head ---
    k_zero_pool<<<(NGRAPH * HID + 255) / 256, 256>>>(pool, cnt);
    {
        long thr = (long)n * 32;
        k_pool_scatter<<<(unsigned)((thr + 255) / 256), 256>>>(bufB, bat, pool, cnt, n);
    }
    k_mlp<<<NGRAPH, 128>>>(pool, cnt, Wf1, bf1, Wf2, bf2, out);
}

// round 5
// speedup vs baseline: 2.9510x; 1.2871x over previous
#include <cuda_runtime.h>
#include <cuda_bf16.h>
#include <cstdint>

// ---------------------------------------------------------------------------
// GCN: h1 = relu((ÂX)W1 + b1); h2 = relu((Âh1)W2 + b2); mean pool; MLP head.
// CSR gather aggregation (atomic-free), multi-block scan, bf16 HMMA GEMMs.
// ---------------------------------------------------------------------------

#define MAX_NODES 100000
#define MAX_EDGES 1700000
#define HID 256
#define NGRAPH 2048
#define SCAN_CHUNK 512
#define MAX_SCAN_BLOCKS ((MAX_NODES + SCAN_CHUNK - 1) / SCAN_CHUNK)

__device__ float g_bufA[(size_t)MAX_NODES * HID];
__device__ float g_bufB[(size_t)MAX_NODES * HID];
__device__ float g_dinv[MAX_NODES];
__device__ float g_pool[NGRAPH * HID];
__device__ float g_cnt[NGRAPH];
__device__ __nv_bfloat16 g_Whi[256 * 256];
__device__ __nv_bfloat16 g_Wlo[256 * 256];
__device__ int   g_cntI[MAX_NODES];
__device__ int   g_rowptr[MAX_NODES + 1];
__device__ int   g_cursor[MAX_NODES];
__device__ int   g_csrc[MAX_EDGES];
__device__ float g_cnorm[MAX_EDGES];
__device__ int   g_partial[MAX_SCAN_BLOCKS];

// ========================= helpers =========================
__device__ __forceinline__ void split1(float a, __nv_bfloat16& hi, __nv_bfloat16& lo) {
    hi = __float2bfloat16_rn(a);
    lo = __float2bfloat16_rn(a - __bfloat162float(hi));
}

#define LDMX4(R, ADDR)                                                          \
    asm volatile("ldmatrix.sync.aligned.m8n8.x4.shared.b16 {%0,%1,%2,%3}, [%4];" \
                 : "=r"((R)[0]), "=r"((R)[1]), "=r"((R)[2]), "=r"((R)[3])        \
                 : "r"(ADDR))

#define MMA16816(D, A, B0, B1)                                                  \
    asm volatile("mma.sync.aligned.m16n8k16.row.col.f32.bf16.bf16.f32 "          \
                 "{%0,%1,%2,%3}, {%4,%5,%6,%7}, {%8,%9}, {%0,%1,%2,%3};"         \
                 : "+f"((D)[0]), "+f"((D)[1]), "+f"((D)[2]), "+f"((D)[3])        \
                 : "r"((A)[0]), "r"((A)[1]), "r"((A)[2]), "r"((A)[3]),           \
                   "r"(B0), "r"(B1))

// ===================== CSR construction =====================
__global__ void k_zero_cnt(int* cnt, int n) {
    int i = blockIdx.x * blockDim.x + threadIdx.x;
    if (i < n) cnt[i] = 0;
}
__global__ void k_count(const int* __restrict__ dst, int* __restrict__ cnt, int nE) {
    int i = blockIdx.x * blockDim.x + threadIdx.x;
    if (i < nE) atomicAdd(&cnt[dst[i]], 1);
}
__global__ void k_dinv(const int* __restrict__ cnt, float* __restrict__ dinv, int n) {
    int i = blockIdx.x * blockDim.x + threadIdx.x;
    if (i < n) dinv[i] = rsqrtf((float)(cnt[i] + 1));
}

// ---- 3-phase scan ----
// phase 1: per-block sums of SCAN_CHUNK elements
__global__ void k_scan_p1(const int* __restrict__ cnt, int* __restrict__ partial, int n) {
    __shared__ int s[256];
    int b = blockIdx.x, t = threadIdx.x;
    int base = b * SCAN_CHUNK;
    int i0 = base + t, i1 = base + 256 + t;
    int v = 0;
    if (i0 < n) v += cnt[i0];
    if (i1 < n) v += cnt[i1];
    s[t] = v;
    __syncthreads();
    #pragma unroll
    for (int off = 128; off > 0; off >>= 1) {
        if (t < off) s[t] += s[t + off];
        __syncthreads();
    }
    if (t == 0) partial[b] = s[0];
}
// phase 2: exclusive scan of <=256 partials in one block
__global__ void k_scan_p2(int* __restrict__ partial, int nb) {
    __shared__ int s[256];
    int t = threadIdx.x;
    int v = (t < nb) ? partial[t] : 0;
    s[t] = v;
    __syncthreads();
    #pragma unroll
    for (int off = 1; off < 256; off <<= 1) {
        int u = (t >= off) ? s[t - off] : 0;
        __syncthreads();
        s[t] += u;
        __syncthreads();
    }
    if (t < nb) partial[t] = s[t] - v;   // exclusive
}
// phase 3: per-block exclusive scan + offset -> rowptr, cursor
__global__ void k_scan_p3(const int* __restrict__ cnt, const int* __restrict__ partial,
                          int* __restrict__ rowptr, int* __restrict__ cursor, int n) {
    __shared__ int s[256];
    int b = blockIdx.x, t = threadIdx.x;
    int base = b * SCAN_CHUNK;
    int i0 = base + 2 * t, i1 = i0 + 1;
    int c0 = (i0 < n) ? cnt[i0] : 0;
    int c1 = (i1 < n) ? cnt[i1] : 0;
    int pairSum = c0 + c1;
    s[t] = pairSum;
    __syncthreads();
    #pragma unroll
    for (int off = 1; off < 256; off <<= 1) {
        int u = (t >= off) ? s[t - off] : 0;
        __syncthreads();
        s[t] += u;
        __syncthreads();
    }
    int pre = s[t] - pairSum + partial[b];   // exclusive prefix for i0
    if (i0 < n) { rowptr[i0] = pre; cursor[i0] = pre; if (i0 == n - 1) rowptr[n] = pre + c0; }
    if (i1 < n) { rowptr[i1] = pre + c0; cursor[i1] = pre + c0; if (i1 == n - 1) rowptr[n] = pre + c0 + c1; }
}

__global__ void k_fill(const int* __restrict__ src, const int* __restrict__ dst,
                       const float* __restrict__ dinv, int* __restrict__ cursor,
                       int* __restrict__ csrc, float* __restrict__ cnorm, int nE) {
    int i = blockIdx.x * blockDim.x + threadIdx.x;
    if (i >= nE) return;
    int s = src[i], d = dst[i];
    int pos = atomicAdd(&cursor[d], 1);
    csrc[pos] = s;
    cnorm[pos] = dinv[s] * dinv[d];
}

// ===================== CSR gather aggregation =====================
__global__ __launch_bounds__(256)
void k_gather128(const float* __restrict__ X, const int* __restrict__ rowptr,
                 const int* __restrict__ csrc, const float* __restrict__ cnorm,
                 const float* __restrict__ dinv, float* __restrict__ OUT, int n) {
    int node = (blockIdx.x * blockDim.x + threadIdx.x) >> 5;
    if (node >= n) return;
    int lane = threadIdx.x & 31;
    float di = dinv[node];
    const float4* Xv = (const float4*)X;
    float4 a = Xv[(size_t)node * 32 + lane];
    float s2 = di * di;
    a.x *= s2; a.y *= s2; a.z *= s2; a.w *= s2;
    int e = rowptr[node], e1 = rowptr[node + 1];
    for (; e + 2 <= e1; e += 2) {
        int   s0 = csrc[e],  s1 = csrc[e + 1];
        float n0 = cnorm[e], n1 = cnorm[e + 1];
        float4 v0 = Xv[(size_t)s0 * 32 + lane];
        float4 v1 = Xv[(size_t)s1 * 32 + lane];
        a.x += n0 * v0.x + n1 * v1.x;
        a.y += n0 * v0.y + n1 * v1.y;
        a.z += n0 * v0.z + n1 * v1.z;
        a.w += n0 * v0.w + n1 * v1.w;
    }
    if (e < e1) {
        int s0 = csrc[e]; float n0 = cnorm[e];
        float4 v0 = Xv[(size_t)s0 * 32 + lane];
        a.x += n0 * v0.x; a.y += n0 * v0.y; a.z += n0 * v0.z; a.w += n0 * v0.w;
    }
    ((float4*)OUT)[(size_t)node * 32 + lane] = a;
}

__global__ __launch_bounds__(256)
void k_gather256(const float* __restrict__ X, const int* __restrict__ rowptr,
                 const int* __restrict__ csrc, const float* __restrict__ cnorm,
                 const float* __restrict__ dinv, float* __restrict__ OUT, int n) {
    int node = (blockIdx.x * blockDim.x + threadIdx.x) >> 5;
    if (node >= n) return;
    int lane = threadIdx.x & 31;
    float di = dinv[node];
    const float4* Xv = (const float4*)X;
    size_t base = (size_t)node * 64 + lane;
    float4 a0 = Xv[base], a1 = Xv[base + 32];
    float s2 = di * di;
    a0.x *= s2; a0.y *= s2; a0.z *= s2; a0.w *= s2;
    a1.x *= s2; a1.y *= s2; a1.z *= s2; a1.w *= s2;
    int e = rowptr[node], e1 = rowptr[node + 1];
    for (; e < e1; ++e) {
        int s = csrc[e]; float nm = cnorm[e];
        size_t sb = (size_t)s * 64 + lane;
        float4 v0 = Xv[sb], v1 = Xv[sb + 32];
        a0.x += nm * v0.x; a0.y += nm * v0.y; a0.z += nm * v0.z; a0.w += nm * v0.w;
        a1.x += nm * v1.x; a1.y += nm * v1.y; a1.z += nm * v1.z; a1.w += nm * v1.w;
    }
    ((float4*)OUT)[base] = a0;
    ((float4*)OUT)[base + 32] = a1;
}

// ================= W prep: fp32 [K][256] -> bf16 hi/lo [256][K] =============
__global__ void k_prep_W(const float* __restrict__ W,
                         __nv_bfloat16* __restrict__ Whi,
                         __nv_bfloat16* __restrict__ Wlo, int K) {
    int idx = blockIdx.x * blockDim.x + threadIdx.x;
    if (idx >= K * 256) return;
    int n = idx / K, k = idx % K;
    float v = W[(size_t)k * 256 + n];
    __nv_bfloat16 hi, lo;
    split1(v, hi, lo);
    Whi[idx] = hi;
    Wlo[idx] = lo;
}

// ===================== tensor-core GEMM (M x K) @ (K x 256) =================
#define BM 128
#define BN 128
#define BK 32
#define LDS_PAD 40

__global__ __launch_bounds__(256, 2)
void k_gemm_mma(const float* __restrict__ A,
                const __nv_bfloat16* __restrict__ Bhi,
                const __nv_bfloat16* __restrict__ Blo,
                const float* __restrict__ bias, float* __restrict__ C,
                int M, int K) {
    __shared__ __align__(16) __nv_bfloat16 sAh[BM * LDS_PAD];
    __shared__ __align__(16) __nv_bfloat16 sAl[BM * LDS_PAD];
    __shared__ __align__(16) __nv_bfloat16 sBh[BN * LDS_PAD];
    __shared__ __align__(16) __nv_bfloat16 sBl[BN * LDS_PAD];

    const int tid = threadIdx.x;
    const int wid = tid >> 5, lane = tid & 31;
    const int warpM = wid & 3;
    const int warpN = wid >> 2;
    const int rowBase = blockIdx.y * BM;
    const int colBase = blockIdx.x * BN;

    float acc[2][8][4];
    #pragma unroll
    for (int i = 0; i < 2; i++)
        #pragma unroll
        for (int j = 0; j < 8; j++)
            #pragma unroll
            for (int q = 0; q < 4; q++) acc[i][j][q] = 0.f;

    const int aRow = warpM * 32 + (lane & 15);
    const int aK   = (lane >> 4) * 8;
    const int bRowBase = warpN * 64 + (lane & 7) + ((lane >> 4) << 3);
    const int bK   = ((lane >> 3) & 1) * 8;

    uint32_t sAh_b = (uint32_t)__cvta_generic_to_shared(sAh);
    uint32_t sAl_b = (uint32_t)__cvta_generic_to_shared(sAl);
    uint32_t sBh_b = (uint32_t)__cvta_generic_to_shared(sBh);
    uint32_t sBl_b = (uint32_t)__cvta_generic_to_shared(sBl);

    for (int k0 = 0; k0 < K; k0 += BK) {
        {
            int r0 = tid >> 3;
            int k4 = (tid & 7) * 4;
            #pragma unroll
            for (int it = 0; it < 4; ++it) {
                int r = r0 + it * 32;
                int gr = rowBase + r;
                float4 v = make_float4(0.f, 0.f, 0.f, 0.f);
                if (gr < M) v = *(const float4*)(A + (size_t)gr * K + k0 + k4);
                __nv_bfloat16 h0, l0, h1, l1, h2, l2, h3, l3;
                split1(v.x, h0, l0); split1(v.y, h1, l1);
                split1(v.z, h2, l2); split1(v.w, h3, l3);
                __nv_bfloat162 H0 = __nv_bfloat162(h0, h1), H1 = __nv_bfloat162(h2, h3);
                __nv_bfloat162 L0 = __nv_bfloat162(l0, l1), L1 = __nv_bfloat162(l2, l3);
                int off = r * LDS_PAD + k4;
                *(uint2*)&sAh[off] = make_uint2(*(uint32_t*)&H0, *(uint32_t*)&H1);
                *(uint2*)&sAl[off] = make_uint2(*(uint32_t*)&L0, *(uint32_t*)&L1);
            }
        }
        {
            #pragma unroll
            for (int it = 0; it < 2; ++it) {
                int i = tid + it * 256;
                int n = i >> 2;
                int kq = (i & 3) * 8;
                int off = n * LDS_PAD + kq;
                const size_t g = (size_t)(colBase + n) * K + k0 + kq;
                *(uint4*)&sBh[off] = *(const uint4*)(Bhi + g);
                *(uint4*)&sBl[off] = *(const uint4*)(Blo + g);
            }
        }
        __syncthreads();

        #pragma unroll
        for (int kk = 0; kk < BK; kk += 16) {
            uint32_t aH[2][4], aL[2][4];
            #pragma unroll
            for (int mi = 0; mi < 2; ++mi) {
                uint32_t o = (uint32_t)((aRow + mi * 16) * LDS_PAD + kk + aK) * 2;
                LDMX4(aH[mi], sAh_b + o);
                LDMX4(aL[mi], sAl_b + o);
            }
            #pragma unroll
            for (int nj = 0; nj < 4; ++nj) {
                uint32_t bH[4], bL[4];
                uint32_t o = (uint32_t)((bRowBase + nj * 16) * LDS_PAD + kk + bK) * 2;
                LDMX4(bH, sBh_b + o);
                LDMX4(bL, sBl_b + o);
                #pragma unroll
                for (int mi = 0; mi < 2; ++mi) {
                    MMA16816(acc[mi][nj * 2 + 0], aH[mi], bH[0], bH[1]);
                    MMA16816(acc[mi][nj * 2 + 1], aH[mi], bH[2], bH[3]);
                    MMA16816(acc[mi][nj * 2 + 0], aH[mi], bL[0], bL[1]);
                    MMA16816(acc[mi][nj * 2 + 1], aH[mi], bL[2], bL[3]);
                    MMA16816(acc[mi][nj * 2 + 0], aL[mi], bH[0], bH[1]);
                    MMA16816(acc[mi][nj * 2 + 1], aL[mi], bH[2], bH[3]);
                }
            }
        }
        __syncthreads();
    }

    const int erow = rowBase + warpM * 32 + (lane >> 2);
    const int ecol = colBase + warpN * 64 + (lane & 3) * 2;
    #pragma unroll
    for (int mi = 0; mi < 2; ++mi) {
        int r0 = erow + mi * 16;
        #pragma unroll
        for (int nj = 0; nj < 8; ++nj) {
            int c = ecol + nj * 8;
            float b0 = bias[c], b1 = bias[c + 1];
            if (r0 < M) {
                float2 v;
                v.x = fmaxf(acc[mi][nj][0] + b0, 0.f);
                v.y = fmaxf(acc[mi][nj][1] + b1, 0.f);
                *(float2*)(C + (size_t)r0 * 256 + c) = v;
            }
            if (r0 + 8 < M) {
                float2 v;
                v.x = fmaxf(acc[mi][nj][2] + b0, 0.f);
                v.y = fmaxf(acc[mi][nj][3] + b1, 0.f);
                *(float2*)(C + (size_t)(r0 + 8) * 256 + c) = v;
            }
        }
    }
}

// ============================== pooling ====================================
__global__ void k_zero_pool(float* pool, float* cnt) {
    int i = blockIdx.x * blockDim.x + threadIdx.x;
    if (i < NGRAPH * HID) pool[i] = 0.f;
    if (i < NGRAPH) cnt[i] = 0.f;
}
__global__ void k_pool_scatter(const float* __restrict__ H, const int* __restrict__ batch,
                               float* __restrict__ pool, float* __restrict__ cnt, int n) {
    int node = (blockIdx.x * blockDim.x + threadIdx.x) >> 5;
    if (node >= n) return;
    int lane = threadIdx.x & 31;
    int g = batch[node];
    const float4* h = (const float4*)(H + (size_t)node * HID);
    float4* pg = (float4*)(pool + (size_t)g * HID);
    #pragma unroll
    for (int i = lane; i < HID / 4; i += 32) {
        float4 v = h[i];
        asm volatile("red.global.add.v4.f32 [%0], {%1,%2,%3,%4};"
                     :: "l"(pg + i), "f"(v.x), "f"(v.y), "f"(v.z), "f"(v.w) : "memory");
    }
    if (lane == 0) atomicAdd(&cnt[g], 1.0f);
}

// ================================ MLP head =================================
__global__ void k_mlp(const float* __restrict__ pool, const float* __restrict__ cnt,
                      const float* __restrict__ Wf1, const float* __restrict__ bf1,
                      const float* __restrict__ Wf2, const float* __restrict__ bf2,
                      float* __restrict__ out) {
    int g = blockIdx.x;
    __shared__ float p[HID];
    __shared__ float red[128];
    int t = threadIdx.x;
    float inv = 1.0f / fmaxf(cnt[g], 1.0f);
    p[t]       = pool[g * HID + t] * inv;
    p[t + 128] = pool[g * HID + 128 + t] * inv;
    __syncthreads();
    float acc = bf1[t];
    #pragma unroll 8
    for (int k = 0; k < HID; k++) acc += p[k] * Wf1[k * 128 + t];
    red[t] = fmaxf(acc, 0.f) * Wf2[t];
    __syncthreads();
    for (int s = 64; s > 0; s >>= 1) {
        if (t < s) red[t] += red[t + s];
        __syncthreads();
    }
    if (t == 0) out[g] = red[0] + bf2[0];
}

// ---------------------------------------------------------------------------
extern "C" void kernel_launch(void* const* d_in, const int* in_sizes, int n_in,
                              void* d_out, int out_size) {
    const float* x   = (const float*)d_in[0];
    const int*   ei  = (const int*)d_in[1];
    const int*   bat = (const int*)d_in[2];
    const float* W1  = (const float*)d_in[3];
    const float* b1  = (const float*)d_in[4];
    const float* W2  = (const float*)d_in[5];
    const float* b2  = (const float*)d_in[6];
    const float* Wf1 = (const float*)d_in[7];
    const float* bf1 = (const float*)d_in[8];
    const float* Wf2 = (const float*)d_in[9];
    const float* bf2 = (const float*)d_in[10];
    float* out = (float*)d_out;

    int n  = in_sizes[0] / 128;
    int nE = in_sizes[1] / 2;
    const int* src = ei;
    const int* dst = ei + nE;

    float *bufA, *bufB, *dinv, *pool, *cnt;
    __nv_bfloat16 *Whi, *Wlo;
    int *cntI, *rowptr, *cursor, *csrc, *partial;
    float *cnorm;
    cudaGetSymbolAddress((void**)&bufA, g_bufA);
    cudaGetSymbolAddress((void**)&bufB, g_bufB);
    cudaGetSymbolAddress((void**)&dinv, g_dinv);
    cudaGetSymbolAddress((void**)&pool, g_pool);
    cudaGetSymbolAddress((void**)&cnt,  g_cnt);
    cudaGetSymbolAddress((void**)&Whi,  g_Whi);
    cudaGetSymbolAddress((void**)&Wlo,  g_Wlo);
    cudaGetSymbolAddress((void**)&cntI, g_cntI);
    cudaGetSymbolAddress((void**)&rowptr, g_rowptr);
    cudaGetSymbolAddress((void**)&cursor, g_cursor);
    cudaGetSymbolAddress((void**)&csrc, g_csrc);
    cudaGetSymbolAddress((void**)&cnorm, g_cnorm);
    cudaGetSymbolAddress((void**)&partial, g_partial);

    // --- CSR build ---
    int nb = (n + SCAN_CHUNK - 1) / SCAN_CHUNK;
    k_zero_cnt<<<(n + 255) / 256, 256>>>(cntI, n);
    k_count<<<(nE + 255) / 256, 256>>>(dst, cntI, nE);
    k_dinv<<<(n + 255) / 256, 256>>>(cntI, dinv, n);
    k_scan_p1<<<nb, 256>>>(cntI, partial, n);
    k_scan_p2<<<1, 256>>>(partial, nb);
    k_scan_p3<<<nb, 256>>>(cntI, partial, rowptr, cursor, n);
    k_fill<<<(nE + 255) / 256, 256>>>(src, dst, dinv, cursor, csrc, cnorm, nE);

    dim3 gemmGrid(2, (n + BM - 1) / BM);
    unsigned gatherBlocks = (unsigned)(((long)n * 32 + 255) / 256);

    // --- layer 1 ---
    k_gather128<<<gatherBlocks, 256>>>(x, rowptr, csrc, cnorm, dinv, bufA, n);
    k_prep_W<<<(128 * 256 + 255) / 256, 256>>>(W1, Whi, Wlo, 128);
    k_gemm_mma<<<gemmGrid, 256>>>(bufA, Whi, Wlo, b1, bufB, n, 128);

    // --- layer 2 ---
    k_gather256<<<gatherBlocks, 256>>>(bufB, rowptr, csrc, cnorm, dinv, bufA, n);
    k_prep_W<<<(256 * 256 + 255) / 256, 256>>>(W2, Whi, Wlo, 256);
    k_gemm_mma<<<gemmGrid, 256>>>(bufA, Whi, Wlo, b2, bufB, n, 256);

    // --- pooling + MLP head ---
    k_zero_pool<<<(NGRAPH * HID + 255) / 256, 256>>>(pool, cnt);
    {
        long thr = (long)n * 32;
        k_pool_scatter<<<(unsigned)((thr + 255) / 256), 256>>>(bufB, bat, pool, cnt, n);
    }
    k_mlp<<<NGRAPH, 128>>>(pool, cnt, Wf1, bf1, Wf2, bf2, out);
}